// round 2
// baseline (speedup 1.0000x reference)
#include <cuda_runtime.h>
#include <math.h>

#define DH 512
#define NB 256
#define RG 196
#define TQ 26
#define NAV 3000

// ---------------- scratch (__device__ globals, no allocation) ----------------
__device__ float g_sumfeat[NB*DH];
__device__ float g_simg[NB*DH];
__device__ float g_word[NB*TQ*DH];
__device__ float g_sumword[NB*DH];
__device__ float g_phrase[NB*TQ*DH];
__device__ float g_sumphrase[NB*DH];
__device__ float g_xg[(size_t)NB*TQ*4*DH];
__device__ float g_gbuf[NB*4*DH];
__device__ float g_h[NB*DH];
__device__ float g_c[NB*DH];
__device__ float g_sumsent[NB*DH];
__device__ float g_pw[NB*DH];
__device__ float g_hw[NB*DH];
__device__ float g_hp[NB*DH];
__device__ float g_hs[NB*DH];
__device__ float g_cat[NB*2*DH];

// ---------------- generic tiled SGEMM ----------------
// C[M,N] = A[M,K] @ B[K,N] (+ epilogue). Assumes M % BM == 0, K % 16 == 0,
// N arbitrary but multiple of 4. Row-major everything.
#define EPI_BIAS 0
#define EPI_TANH 1
#define EPI_ADDMAT 2
#define EPI_BIAS_SCALE 3

template<int BM,int BN,int TM,int TN,int EPI>
__global__ __launch_bounds__(256)
void gemm_k(const float* __restrict__ A, const float* __restrict__ Bm,
            const float* __restrict__ bias, const float* __restrict__ Dmat,
            float* __restrict__ C, int M, int N, int K,
            int lda, int ldb, int ldc, int ldd, float bscale)
{
    constexpr int BK = 16;
    constexpr int TX = BN / TN;
    constexpr int THREADS = (BM/TM)*(BN/TN);
    __shared__ float As[BK][BM+4];
    __shared__ float Bs[BK][BN];
    const int tid = threadIdx.x;
    const int m0 = blockIdx.y * BM, n0 = blockIdx.x * BN;
    const int tn = tid % TX, tm = tid / TX;
    float acc[TM][TN];
#pragma unroll
    for (int i = 0; i < TM; i++)
#pragma unroll
        for (int j = 0; j < TN; j++) acc[i][j] = 0.f;

    constexpr int A_PER = (BM*BK/4)/THREADS;   // float4 loads per thread (A)
    constexpr int B_PER = (BK*BN/4)/THREADS;   // float4 loads per thread (B)

    for (int k0 = 0; k0 < K; k0 += BK) {
#pragma unroll
        for (int j = 0; j < A_PER; j++) {
            int idx = tid + j*THREADS;
            int row = idx >> 2, kq = (idx & 3) << 2;
            float4 v = *(const float4*)(A + (size_t)(m0+row)*lda + k0 + kq);
            As[kq+0][row]=v.x; As[kq+1][row]=v.y; As[kq+2][row]=v.z; As[kq+3][row]=v.w;
        }
#pragma unroll
        for (int j = 0; j < B_PER; j++) {
            int idx = tid + j*THREADS;
            int krow = idx / (BN/4), nq = (idx % (BN/4)) << 2;
            float4 v;
            if (n0 + nq < N) v = *(const float4*)(Bm + (size_t)(k0+krow)*ldb + n0 + nq);
            else             v = make_float4(0.f,0.f,0.f,0.f);
            *(float4*)(&Bs[krow][nq]) = v;
        }
        __syncthreads();
#pragma unroll
        for (int kk = 0; kk < BK; kk++) {
            float a[TM], b[TN];
#pragma unroll
            for (int i = 0; i < TM; i += 4) {
                float4 v = *(const float4*)(&As[kk][tm*TM + i]);
                a[i]=v.x; a[i+1]=v.y; a[i+2]=v.z; a[i+3]=v.w;
            }
#pragma unroll
            for (int j = 0; j < TN; j += 4) {
                float4 v = *(const float4*)(&Bs[kk][tn*TN + j]);
                b[j]=v.x; b[j+1]=v.y; b[j+2]=v.z; b[j+3]=v.w;
            }
#pragma unroll
            for (int i = 0; i < TM; i++)
#pragma unroll
                for (int j = 0; j < TN; j++) acc[i][j] = fmaf(a[i], b[j], acc[i][j]);
        }
        __syncthreads();
    }

#pragma unroll
    for (int i = 0; i < TM; i++) {
        int m = m0 + tm*TM + i;
#pragma unroll
        for (int j = 0; j < TN; j++) {
            int n = n0 + tn*TN + j;
            if (n < N) {
                float v = acc[i][j];
                if (EPI == EPI_BIAS)        v += bias[n];
                else if (EPI == EPI_TANH)   v = tanhf(v + bias[n]);
                else if (EPI == EPI_ADDMAT) v += Dmat[(size_t)m*ldd + n];
                else if (EPI == EPI_BIAS_SCALE) v += bias[n]*bscale;
                C[(size_t)m*ldc + n] = v;
            }
        }
    }
}

// ---------------- fused n-gram conv (uni/bi/tri) + max ----------------
// For row m=(b,t), virtual window win[k], k in [0,1536): value = word_flat[m*512 + k - 512]
// valid unless (t==0 && k<512) or (t==T-1 && k>=1024).
//   tri uses W_tri[k][n] over k in [0,1536)
//   bi  uses W_bi[k-256][n] over k in [256,1280)
//   uni uses W_uni[k-512][n] over k in [512,1024)
// phrase = max(uni+bu, bi+bb, tri+bt)
__global__ __launch_bounds__(256)
void phrase_kernel(const float* __restrict__ word,
                   const float* __restrict__ Wu, const float* __restrict__ Wb,
                   const float* __restrict__ Wt,
                   const float* __restrict__ bu, const float* __restrict__ bb,
                   const float* __restrict__ bt,
                   float* __restrict__ out)
{
    constexpr int BM=64, BN=64, BK=16, TM=4, TN=4;
    __shared__ float As[BK][BM+4];
    __shared__ float Bts[BK][BN];
    __shared__ float Bbs[BK][BN];
    __shared__ float Bus[BK][BN];
    const int tid = threadIdx.x;
    const int m0 = blockIdx.y * BM, n0 = blockIdx.x * BN;
    const int tn = tid & 15, tm = tid >> 4;
    float at[TM][TN], ab[TM][TN], au[TM][TN];
#pragma unroll
    for (int i = 0; i < TM; i++)
#pragma unroll
        for (int j = 0; j < TN; j++) { at[i][j]=0.f; ab[i][j]=0.f; au[i][j]=0.f; }

    const int lrow = tid >> 2, lkq = (tid & 3) << 2;
    const int row_g = m0 + lrow;
    const int t_idx = row_g % TQ;
    const float* arow = word + (size_t)row_g * DH - DH; // virtual offset -512
    const int bkrow = tid >> 4, bnq = (tid & 15) << 2;

    for (int k0 = 0; k0 < 3*DH; k0 += BK) {
        bool valid = !((t_idx == 0) && (k0 < DH)) && !((t_idx == TQ-1) && (k0 >= 2*DH));
        float4 v = valid ? *(const float4*)(arow + k0 + lkq) : make_float4(0.f,0.f,0.f,0.f);
        As[lkq+0][lrow]=v.x; As[lkq+1][lrow]=v.y; As[lkq+2][lrow]=v.z; As[lkq+3][lrow]=v.w;

        int kg = k0 + bkrow;
        *(float4*)(&Bts[bkrow][bnq]) = *(const float4*)(Wt + (size_t)kg*DH + n0 + bnq);
        const bool hasb = (k0 >= 256) && (k0 < 1280);
        const bool hasu = (k0 >= 512) && (k0 < 1024);
        if (hasb) *(float4*)(&Bbs[bkrow][bnq]) = *(const float4*)(Wb + (size_t)(kg-256)*DH + n0 + bnq);
        if (hasu) *(float4*)(&Bus[bkrow][bnq]) = *(const float4*)(Wu + (size_t)(kg-512)*DH + n0 + bnq);
        __syncthreads();

#pragma unroll
        for (int kk = 0; kk < BK; kk++) {
            float a[TM];
            float4 va = *(const float4*)(&As[kk][tm*TM]);
            a[0]=va.x; a[1]=va.y; a[2]=va.z; a[3]=va.w;
            float4 vt = *(const float4*)(&Bts[kk][tn*TN]);
            float b4[4] = {vt.x, vt.y, vt.z, vt.w};
#pragma unroll
            for (int i = 0; i < 4; i++)
#pragma unroll
                for (int j = 0; j < 4; j++) at[i][j] = fmaf(a[i], b4[j], at[i][j]);
            if (hasb) {
                float4 vb = *(const float4*)(&Bbs[kk][tn*TN]);
                float c4[4] = {vb.x, vb.y, vb.z, vb.w};
#pragma unroll
                for (int i = 0; i < 4; i++)
#pragma unroll
                    for (int j = 0; j < 4; j++) ab[i][j] = fmaf(a[i], c4[j], ab[i][j]);
            }
            if (hasu) {
                float4 vu = *(const float4*)(&Bus[kk][tn*TN]);
                float u4[4] = {vu.x, vu.y, vu.z, vu.w};
#pragma unroll
                for (int i = 0; i < 4; i++)
#pragma unroll
                    for (int j = 0; j < 4; j++) au[i][j] = fmaf(a[i], u4[j], au[i][j]);
            }
        }
        __syncthreads();
    }

#pragma unroll
    for (int i = 0; i < TM; i++) {
        int m = m0 + tm*TM + i;
#pragma unroll
        for (int j = 0; j < TN; j++) {
            int n = n0 + tn*TN + j;
            float v = fmaxf(fmaxf(au[i][j] + bu[n], ab[i][j] + bb[n]), at[i][j] + bt[n]);
            out[(size_t)m*DH + n] = v;
        }
    }
}

// ---------------- small kernels ----------------
__global__ void reduce_img_k(const float* __restrict__ im, float* __restrict__ out) {
    int b = blockIdx.x;
    int d4 = threadIdx.x; // 128 threads, one float4 each
    const float4* p = (const float4*)(im + (size_t)b*RG*DH) + d4;
    float4 s = make_float4(0.f,0.f,0.f,0.f);
    for (int r = 0; r < RG; r++) {
        float4 v = p[(size_t)r*(DH/4)];
        s.x+=v.x; s.y+=v.y; s.z+=v.z; s.w+=v.w;
    }
    ((float4*)(out + (size_t)b*DH))[d4] = s;
}

__global__ void gather_k(const int* __restrict__ q, const float* __restrict__ emb,
                         float* __restrict__ word) {
    int row = blockIdx.x;
    int qi = q[row];
    const float4* s = (const float4*)(emb + (size_t)qi*DH);
    float4* d = (float4*)(word + (size_t)row*DH);
    d[threadIdx.x] = s[threadIdx.x]; // 128 threads * float4 = 512
}

__global__ void sum_t_k(const float* __restrict__ src, float* __restrict__ dst) {
    int b = blockIdx.x, d = threadIdx.x; // 512 threads
    float s = 0.f;
    for (int t = 0; t < TQ; t++) s += src[((size_t)b*TQ + t)*DH + d];
    dst[(size_t)b*DH + d] = s;
}

__global__ void zero3_k(float* a, float* b, float* c) {
    int i = blockIdx.x*blockDim.x + threadIdx.x;
    a[i] = 0.f; b[i] = 0.f; c[i] = 0.f;
}

__device__ __forceinline__ float sigm(float x) { return 1.f / (1.f + expf(-x)); }

__global__ void lstm_update_k(const float* __restrict__ g, float* __restrict__ h,
                              float* __restrict__ c, float* __restrict__ ss) {
    int idx = blockIdx.x*blockDim.x + threadIdx.x; // NB*DH
    int b = idx >> 9, d = idx & 511;
    const float* gr = g + (size_t)b*4*DH;
    float iv = sigm(gr[d]);
    float fv = sigm(gr[DH + d]);
    float cg = tanhf(gr[2*DH + d]);
    float ov = sigm(gr[3*DH + d]);
    float cn = fv*c[idx] + iv*cg;
    float hn = ov*tanhf(cn);
    c[idx] = cn; h[idx] = hn; ss[idx] += hn;
}

__global__ void add2_k(const float* __restrict__ a, const float* __restrict__ b,
                       float* __restrict__ o) {
    int i = blockIdx.x*blockDim.x + threadIdx.x;
    o[i] = a[i] + b[i];
}

__global__ void cat_k(const float* __restrict__ a, const float* __restrict__ b,
                      const float* __restrict__ h, float* __restrict__ o) {
    int i = blockIdx.x*blockDim.x + threadIdx.x; // NB*DH
    int bb = i >> 9, d = i & 511;
    o[(size_t)bb*2*DH + d]      = a[i] + b[i];
    o[(size_t)bb*2*DH + DH + d] = h[i];
}

// ---------------- driver ----------------
static float* sym(const void* s) { void* p = nullptr; cudaGetSymbolAddress(&p, s); return (float*)p; }

extern "C" void kernel_launch(void* const* d_in, const int* in_sizes, int n_in,
                              void* d_out, int out_size)
{
    const float* image_feat = (const float*)d_in[0];
    const int*   q_enc      = (const int*)  d_in[1];
    const float* W_ip  = (const float*)d_in[2];
    const float* b_ip  = (const float*)d_in[3];
    const float* emb   = (const float*)d_in[4];
    const float* W_uni = (const float*)d_in[5];
    const float* b_uni = (const float*)d_in[6];
    const float* W_bi  = (const float*)d_in[7];
    const float* b_bi  = (const float*)d_in[8];
    const float* W_tri = (const float*)d_in[9];
    const float* b_tri = (const float*)d_in[10];
    const float* Wx    = (const float*)d_in[11];
    const float* Wh    = (const float*)d_in[12];
    const float* b_lstm= (const float*)d_in[13];
    // d_in[14..23]: W_c,b_c,W_v,b_v,W_q,b_q,W_ai,b_ai,W_at,b_at — DEAD (softmax over size-1 axis)
    const float* W_w = (const float*)d_in[24];
    const float* b_w = (const float*)d_in[25];
    const float* W_p = (const float*)d_in[26];
    const float* b_p = (const float*)d_in[27];
    const float* W_s = (const float*)d_in[28];
    const float* b_s = (const float*)d_in[29];
    const float* W_f = (const float*)d_in[30];
    const float* b_f = (const float*)d_in[31];
    float* out = (float*)d_out;

    float* p_sumfeat   = sym(g_sumfeat);
    float* p_simg      = sym(g_simg);
    float* p_word      = sym(g_word);
    float* p_sumword   = sym(g_sumword);
    float* p_phrase    = sym(g_phrase);
    float* p_sumphrase = sym(g_sumphrase);
    float* p_xg        = sym(g_xg);
    float* p_gbuf      = sym(g_gbuf);
    float* p_h         = sym(g_h);
    float* p_c         = sym(g_c);
    float* p_sumsent   = sym(g_sumsent);
    float* p_pw        = sym(g_pw);
    float* p_hw        = sym(g_hw);
    float* p_hp        = sym(g_hp);
    float* p_hs        = sym(g_hs);
    float* p_cat       = sym(g_cat);

    const int BT = NB*TQ;           // 6656
    const int BD = NB*DH;           // 131072

    // 1) sum image over regions, project: s_img = (Σ_r image_feat) @ W_ip + R*b_ip
    reduce_img_k<<<NB, 128>>>(image_feat, p_sumfeat);
    gemm_k<64,64,4,4,EPI_BIAS_SCALE><<<dim3(DH/64, NB/64), 256>>>(
        p_sumfeat, W_ip, b_ip, nullptr, p_simg, NB, DH, DH, DH, DH, DH, 0, (float)RG);

    // 2) word embedding gather + Σ_t word
    gather_k<<<BT, 128>>>(q_enc, emb, p_word);
    sum_t_k<<<NB, DH>>>(p_word, p_sumword);

    // 3) fused n-gram convs + max -> phrase
    phrase_kernel<<<dim3(DH/64, BT/64), 256>>>(
        p_word, W_uni, W_bi, W_tri, b_uni, b_bi, b_tri, p_phrase);
    sum_t_k<<<NB, DH>>>(p_phrase, p_sumphrase);

    // 4) xg = phrase @ Wx + b_lstm
    gemm_k<128,64,8,4,EPI_BIAS><<<dim3(4*DH/64, BT/128), 256>>>(
        p_phrase, Wx, b_lstm, nullptr, p_xg, BT, 4*DH, DH, DH, 4*DH, 4*DH, 0, 0.f);

    // 5) LSTM over T steps; accumulate Σ_t h into sumsent
    zero3_k<<<BD/256, 256>>>(p_h, p_c, p_sumsent);
    for (int t = 0; t < TQ; t++) {
        gemm_k<64,64,4,4,EPI_ADDMAT><<<dim3(4*DH/64, NB/64), 256>>>(
            p_h, Wh, nullptr, p_xg + (size_t)t*4*DH, p_gbuf,
            NB, 4*DH, DH, DH, 4*DH, 4*DH, TQ*4*DH, 0.f);
        lstm_update_k<<<BD/256, 256>>>(p_gbuf, p_h, p_c, p_sumsent);
    }

    // 6) heads (pool = plain sums since softmax over a single logit == 1)
    add2_k<<<BD/256, 256>>>(p_simg, p_sumword, p_pw);
    gemm_k<64,64,4,4,EPI_TANH><<<dim3(DH/64, NB/64), 256>>>(
        p_pw, W_w, b_w, nullptr, p_hw, NB, DH, DH, DH, DH, DH, 0, 0.f);

    cat_k<<<BD/256, 256>>>(p_simg, p_sumphrase, p_hw, p_cat);
    gemm_k<64,64,4,4,EPI_TANH><<<dim3(DH/64, NB/64), 256>>>(
        p_cat, W_p, b_p, nullptr, p_hp, NB, DH, 2*DH, 2*DH, DH, DH, 0, 0.f);

    cat_k<<<BD/256, 256>>>(p_simg, p_sumsent, p_hp, p_cat);
    gemm_k<64,64,4,4,EPI_TANH><<<dim3(DH/64, NB/64), 256>>>(
        p_cat, W_s, b_s, nullptr, p_hs, NB, DH, 2*DH, 2*DH, DH, DH, 0, 0.f);

    // 7) final projection to answer vocab
    gemm_k<64,64,4,4,EPI_BIAS><<<dim3((NAV+63)/64, NB/64), 256>>>(
        p_hs, W_f, b_f, nullptr, out, NB, NAV, DH, DH, NAV, NAV, 0, 0.f);
}

// round 16
// speedup vs baseline: 1.1449x; 1.1449x over previous
#include <cuda_runtime.h>
#include <cuda_bf16.h>
#include <math.h>
#include <stdint.h>

#define DH 512
#define NB 256
#define RG 196
#define TQ 26
#define NAV 3000
#define NAVP 3072

// ================= scratch =================
__device__ float g_sumfeat[NB*DH];
__device__ float g_simg[NB*DH];
__device__ float g_word[NB*TQ*DH];
__device__ float g_sumword[NB*DH];
__device__ float g_phrase[NB*TQ*DH];
__device__ float g_sumphrase[NB*DH];
__device__ float g_xg[(size_t)NB*TQ*4*DH];   // also reused as 3 conv temps before xg
__device__ float g_h[NB*DH];
__device__ float g_h2[NB*DH];
__device__ float g_c[NB*DH];
__device__ float g_ss[NB*DH];
__device__ float g_pw[NB*DH];
__device__ float g_hw[NB*DH];
__device__ float g_hp[NB*DH];
__device__ float g_hs[NB*DH];
__device__ float g_cat[NB*2*DH];
__device__ float g_blp[4*DH];

// transposed bf16 hi/lo weights ([N,K] layout, K contiguous)
__device__ __nv_bfloat16 g_tri_h[512*1536], g_tri_l[512*1536];
__device__ __nv_bfloat16 g_bi_h [512*1024], g_bi_l [512*1024];
__device__ __nv_bfloat16 g_uni_h[512*512],  g_uni_l[512*512];
__device__ __nv_bfloat16 g_wx_h [2048*512], g_wx_l [2048*512];
__device__ __nv_bfloat16 g_wh_h [2048*512], g_wh_l [2048*512];
__device__ __nv_bfloat16 g_wip_h[512*512],  g_wip_l[512*512];
__device__ __nv_bfloat16 g_ww_h [512*512],  g_ww_l [512*512];
__device__ __nv_bfloat16 g_wp_h [512*1024], g_wp_l [512*1024];
__device__ __nv_bfloat16 g_ws_h [512*1024], g_ws_l [512*1024];
__device__ __nv_bfloat16 g_wf_h [NAVP*512], g_wf_l [NAVP*512];

// ================= helpers =================
__device__ __forceinline__ uint32_t smem_u32(const void* p) {
    uint32_t a;
    asm("{ .reg .u64 t; cvta.to.shared.u64 t, %1; cvt.u32.u64 %0, t; }" : "=r"(a) : "l"(p));
    return a;
}

#define LDSM4(r, a) \
    asm volatile("ldmatrix.sync.aligned.m8n8.x4.shared.b16 {%0,%1,%2,%3}, [%4];" \
        : "=r"((r)[0]), "=r"((r)[1]), "=r"((r)[2]), "=r"((r)[3]) : "r"(a))
#define LDSM2(r, a) \
    asm volatile("ldmatrix.sync.aligned.m8n8.x2.shared.b16 {%0,%1}, [%2];" \
        : "=r"((r)[0]), "=r"((r)[1]) : "r"(a))
#define MMA(d, a, b) \
    asm volatile("mma.sync.aligned.m16n8k16.row.col.f32.bf16.bf16.f32 " \
        "{%0,%1,%2,%3}, {%4,%5,%6,%7}, {%8,%9}, {%0,%1,%2,%3};" \
        : "+f"((d)[0]), "+f"((d)[1]), "+f"((d)[2]), "+f"((d)[3]) \
        : "r"((a)[0]), "r"((a)[1]), "r"((a)[2]), "r"((a)[3]), "r"((b)[0]), "r"((b)[1]))

__device__ __forceinline__ float sigm(float x) { return 1.f / (1.f + expf(-x)); }

// store float4 as bf16 hi (8B) + lo (8B)
__device__ __forceinline__ void cvt_store4(char* hi, char* lo, uint32_t off, float4 v) {
    unsigned short h0 = __bfloat16_as_ushort(__float2bfloat16(v.x));
    unsigned short h1 = __bfloat16_as_ushort(__float2bfloat16(v.y));
    unsigned short h2 = __bfloat16_as_ushort(__float2bfloat16(v.z));
    unsigned short h3 = __bfloat16_as_ushort(__float2bfloat16(v.w));
    float r0 = v.x - __bfloat162float(__ushort_as_bfloat16(h0));
    float r1 = v.y - __bfloat162float(__ushort_as_bfloat16(h1));
    float r2 = v.z - __bfloat162float(__ushort_as_bfloat16(h2));
    float r3 = v.w - __bfloat162float(__ushort_as_bfloat16(h3));
    unsigned short l0 = __bfloat16_as_ushort(__float2bfloat16(r0));
    unsigned short l1 = __bfloat16_as_ushort(__float2bfloat16(r1));
    unsigned short l2 = __bfloat16_as_ushort(__float2bfloat16(r2));
    unsigned short l3 = __bfloat16_as_ushort(__float2bfloat16(r3));
    *(uint2*)(hi + off) = make_uint2(((uint32_t)h1 << 16) | h0, ((uint32_t)h3 << 16) | h2);
    *(uint2*)(lo + off) = make_uint2(((uint32_t)l1 << 16) | l0, ((uint32_t)l3 << 16) | l2);
}

// ================= mma.sync GEMM =================
// C[M,N] = A[M,K](f32) @ B^T (B [N,K] bf16 hi/lo), hi/lo 3-pass.
// BM=128, BN=64, BK=32. 256 thr, 8 warps (4M x 2N), warp tile 32x32.
// conv!=0: A is a windowed view of word: A[m][k] = word[m*DH + woff + k - DH],
//          invalid (0) if (g<0 && t==0) or (g>=DH && t==TQ-1), g=woff+k-DH, t=m%TQ.
#define EPI_BIAS 0
#define EPI_TANH 1
#define EPI_BSCL 2
#define EPI_LSTM 3

#define ASTR 40   // smem row stride in bf16 elems (80 bytes) — conflict-free for ldmatrix

template<int EPI>
__global__ __launch_bounds__(256)
void gemm_mma(const float* __restrict__ A,
              const __nv_bfloat16* __restrict__ Bhi, const __nv_bfloat16* __restrict__ Blo,
              const float* __restrict__ bias, const float* __restrict__ Dmat,
              float* __restrict__ C, float* __restrict__ cbuf, float* __restrict__ ssbuf,
              int Nstore, int K, int lda, int ldc, int ldd, float bscale,
              int conv, int woff)
{
    __shared__ __nv_bfloat16 sAh[128*ASTR], sAl[128*ASTR];
    __shared__ __nv_bfloat16 sBh[64*ASTR],  sBl[64*ASTR];
    const int tid = threadIdx.x, wid = tid >> 5, lane = tid & 31;
    const int wm = wid & 3, wn = wid >> 2;          // 4 warps M, 2 warps N
    const int m0 = blockIdx.y * 128, n0 = blockIdx.x * 64;

    const uint32_t aSh = smem_u32(sAh), aSl = smem_u32(sAl);
    const uint32_t bSh = smem_u32(sBh), bSl = smem_u32(sBl);

    float acc[2][4][4];
#pragma unroll
    for (int mt = 0; mt < 2; mt++)
#pragma unroll
        for (int nt = 0; nt < 4; nt++)
#pragma unroll
            for (int i = 0; i < 4; i++) acc[mt][nt][i] = 0.f;

    const int arow = tid >> 1, acol0 = (tid & 1) * 16;   // A: 2 thr/row, 16 elems each
    const int brow = tid >> 2, bk0 = (tid & 3) * 8;      // B: 4 thr/row, 8 elems each
    const int t_idx = conv ? ((m0 + arow) % TQ) : 0;

    for (int k0 = 0; k0 < K; k0 += 32) {
        // ---- load A chunk (f32 -> bf16 hi/lo) ----
#pragma unroll
        for (int q = 0; q < 4; q++) {
            int col = acol0 + q * 4, kg = k0 + col;
            float4 v;
            if (conv) {
                int g = woff + kg - DH;
                bool valid = (g >= 0 || t_idx > 0) && (g < DH || t_idx < TQ - 1);
                v = valid ? *(const float4*)(A + (long)(m0 + arow) * DH + g)
                          : make_float4(0.f, 0.f, 0.f, 0.f);
            } else {
                v = *(const float4*)(A + (size_t)(m0 + arow) * lda + kg);
            }
            cvt_store4((char*)sAh, (char*)sAl, arow * 80 + col * 2, v);
        }
        // ---- load B chunk (bf16 hi/lo) ----
        {
            uint32_t off = brow * 80 + bk0 * 2;
            *(uint4*)((char*)sBh + off) = *(const uint4*)(Bhi + (size_t)(n0 + brow) * K + k0 + bk0);
            *(uint4*)((char*)sBl + off) = *(const uint4*)(Blo + (size_t)(n0 + brow) * K + k0 + bk0);
        }
        __syncthreads();

#pragma unroll
        for (int ks = 0; ks < 2; ks++) {
            uint32_t Ah[2][4], Al[2][4], Bh_[4][2], Bl_[4][2];
#pragma unroll
            for (int mt = 0; mt < 2; mt++) {
                uint32_t o = (uint32_t)(wm * 32 + mt * 16 + (lane & 15)) * 80
                           + ks * 32 + ((lane >> 4) * 16);
                LDSM4(Ah[mt], aSh + o);
                LDSM4(Al[mt], aSl + o);
            }
#pragma unroll
            for (int nt = 0; nt < 4; nt++) {
                uint32_t o = (uint32_t)(wn * 32 + nt * 8 + (lane & 7)) * 80
                           + ks * 32 + (((lane >> 3) & 1) * 16);
                LDSM2(Bh_[nt], bSh + o);
                LDSM2(Bl_[nt], bSl + o);
            }
#pragma unroll
            for (int mt = 0; mt < 2; mt++)
#pragma unroll
                for (int nt = 0; nt < 4; nt++) {
                    MMA(acc[mt][nt], Ah[mt], Bh_[nt]);
                    MMA(acc[mt][nt], Ah[mt], Bl_[nt]);
                    MMA(acc[mt][nt], Al[mt], Bh_[nt]);
                }
        }
        __syncthreads();
    }

    // ---- epilogue ----
#pragma unroll
    for (int mt = 0; mt < 2; mt++) {
#pragma unroll
        for (int nt = 0; nt < 4; nt++) {
            int r0 = m0 + wm * 32 + mt * 16 + (lane >> 2);
            int r1 = r0 + 8;
            int c0 = n0 + wn * 32 + nt * 8 + (lane & 3) * 2;
            int c1 = c0 + 1;
            float v0 = acc[mt][nt][0], v1 = acc[mt][nt][1];
            float v2 = acc[mt][nt][2], v3 = acc[mt][nt][3];
            if (EPI == EPI_LSTM) {
                v0 += Dmat[(size_t)r0 * ldd + c0];
                v1 += Dmat[(size_t)r0 * ldd + c1];
                v2 += Dmat[(size_t)r1 * ldd + c0];
                v3 += Dmat[(size_t)r1 * ldd + c1];
                float e0 = __shfl_xor_sync(0xffffffffu, v0, 1);
                float e1 = __shfl_xor_sync(0xffffffffu, v1, 1);
                float e2 = __shfl_xor_sync(0xffffffffu, v2, 1);
                float e3 = __shfl_xor_sync(0xffffffffu, v3, 1);
                if ((lane & 1) == 0) {
                    int d = c0 >> 2;  // permuted layout: col = d*4 + gate
                    {
                        float cn = sigm(v1) * cbuf[r0 * DH + d] + sigm(v0) * tanhf(e0);
                        float hn = sigm(e1) * tanhf(cn);
                        cbuf[r0 * DH + d] = cn; C[r0 * DH + d] = hn; ssbuf[r0 * DH + d] += hn;
                    }
                    {
                        float cn = sigm(v3) * cbuf[r1 * DH + d] + sigm(v2) * tanhf(e2);
                        float hn = sigm(e3) * tanhf(cn);
                        cbuf[r1 * DH + d] = cn; C[r1 * DH + d] = hn; ssbuf[r1 * DH + d] += hn;
                    }
                }
            } else {
                float b0 = 0.f, b1 = 0.f;
                if (c0 < Nstore) b0 = bias[c0];
                if (c1 < Nstore) b1 = bias[c1];
                if (EPI == EPI_BIAS)      { v0 += b0; v1 += b1; v2 += b0; v3 += b1; }
                else if (EPI == EPI_TANH) { v0 = tanhf(v0 + b0); v1 = tanhf(v1 + b1);
                                            v2 = tanhf(v2 + b0); v3 = tanhf(v3 + b1); }
                else if (EPI == EPI_BSCL) { v0 += b0 * bscale; v1 += b1 * bscale;
                                            v2 += b0 * bscale; v3 += b1 * bscale; }
                if (c0 < Nstore) { C[(size_t)r0 * ldc + c0] = v0; C[(size_t)r1 * ldc + c0] = v2; }
                if (c1 < Nstore) { C[(size_t)r0 * ldc + c1] = v1; C[(size_t)r1 * ldc + c1] = v3; }
            }
        }
    }
}

// ================= transpose + hi/lo split: src[K,N] f32 -> dst[Npad,K] bf16 =================
__global__ void transp_hilo(const float* __restrict__ src,
                            __nv_bfloat16* __restrict__ dh, __nv_bfloat16* __restrict__ dl,
                            int K, int N, int Npad, int perm)
{
    __shared__ float t[32][33];
    int n = blockIdx.x * 32 + threadIdx.x;
#pragma unroll
    for (int i = 0; i < 4; i++) {
        int k = blockIdx.y * 32 + threadIdx.y + i * 8;
        float v = (k < K && n < N) ? src[(size_t)k * N + n] : 0.f;
        t[threadIdx.y + i * 8][threadIdx.x] = v;
    }
    __syncthreads();
#pragma unroll
    for (int i = 0; i < 4; i++) {
        int n2 = blockIdx.x * 32 + threadIdx.y + i * 8;
        int k2 = blockIdx.y * 32 + threadIdx.x;
        if (n2 < Npad && k2 < K) {
            float v = t[threadIdx.x][threadIdx.y + i * 8];
            int q = perm ? (((n2 & 511) << 2) | (n2 >> 9)) : n2;
            __nv_bfloat16 h = __float2bfloat16(v);
            __nv_bfloat16 l = __float2bfloat16(v - __bfloat162float(h));
            dh[(size_t)q * K + k2] = h;
            dl[(size_t)q * K + k2] = l;
        }
    }
}

// ================= small kernels =================
__global__ void reduce_img_k(const float* __restrict__ im, float* __restrict__ out) {
    int b = blockIdx.x, d4 = threadIdx.x;
    const float4* p = (const float4*)(im + (size_t)b * RG * DH) + d4;
    float4 s = make_float4(0.f, 0.f, 0.f, 0.f);
    for (int r = 0; r < RG; r++) {
        float4 v = p[(size_t)r * (DH / 4)];
        s.x += v.x; s.y += v.y; s.z += v.z; s.w += v.w;
    }
    ((float4*)(out + (size_t)b * DH))[d4] = s;
}
__global__ void gather_k(const int* __restrict__ q, const float* __restrict__ emb,
                         float* __restrict__ word) {
    int row = blockIdx.x;
    const float4* s = (const float4*)(emb + (size_t)q[row] * DH);
    ((float4*)(word + (size_t)row * DH))[threadIdx.x] = s[threadIdx.x];
}
__global__ void sum_t_k(const float* __restrict__ src, float* __restrict__ dst) {
    int b = blockIdx.x, d = threadIdx.x;
    float s = 0.f;
    for (int t = 0; t < TQ; t++) s += src[((size_t)b * TQ + t) * DH + d];
    dst[(size_t)b * DH + d] = s;
}
__global__ void zero3_k(float* a, float* b, float* c) {
    int i = blockIdx.x * blockDim.x + threadIdx.x;
    a[i] = 0.f; b[i] = 0.f; c[i] = 0.f;
}
__global__ void add2_k(const float* __restrict__ a, const float* __restrict__ b,
                       float* __restrict__ o) {
    int i = blockIdx.x * blockDim.x + threadIdx.x;
    o[i] = a[i] + b[i];
}
__global__ void cat_k(const float* __restrict__ a, const float* __restrict__ b,
                      const float* __restrict__ h, float* __restrict__ o) {
    int i = blockIdx.x * blockDim.x + threadIdx.x;
    int bb = i >> 9, d = i & 511;
    o[(size_t)bb * 2 * DH + d]      = a[i] + b[i];
    o[(size_t)bb * 2 * DH + DH + d] = h[i];
}
__global__ void biasperm_k(const float* __restrict__ b, float* __restrict__ o) {
    int i = blockIdx.x * blockDim.x + threadIdx.x; // 2048
    o[i] = b[((i & 3) << 9) | (i >> 2)];
}
__global__ void max3_k(const float* __restrict__ u, const float* __restrict__ b,
                       const float* __restrict__ t, float* __restrict__ o) {
    int i = blockIdx.x * blockDim.x + threadIdx.x;
    o[i] = fmaxf(fmaxf(u[i], b[i]), t[i]);
}

// ================= driver =================
#define SYM(p, s) do { void* _t = nullptr; cudaGetSymbolAddress(&_t, s); p = (decltype(p))_t; } while (0)

extern "C" void kernel_launch(void* const* d_in, const int* in_sizes, int n_in,
                              void* d_out, int out_size)
{
    const float* image_feat = (const float*)d_in[0];
    const int*   q_enc      = (const int*)  d_in[1];
    const float* W_ip  = (const float*)d_in[2];
    const float* b_ip  = (const float*)d_in[3];
    const float* emb   = (const float*)d_in[4];
    const float* W_uni = (const float*)d_in[5];
    const float* b_uni = (const float*)d_in[6];
    const float* W_bi  = (const float*)d_in[7];
    const float* b_bi  = (const float*)d_in[8];
    const float* W_tri = (const float*)d_in[9];
    const float* b_tri = (const float*)d_in[10];
    const float* Wx    = (const float*)d_in[11];
    const float* Wh    = (const float*)d_in[12];
    const float* b_lstm= (const float*)d_in[13];
    // d_in[14..23] dead (softmax over size-1 logit -> pool == plain sum)
    const float* W_w = (const float*)d_in[24];
    const float* b_w = (const float*)d_in[25];
    const float* W_p = (const float*)d_in[26];
    const float* b_p = (const float*)d_in[27];
    const float* W_s = (const float*)d_in[28];
    const float* b_s = (const float*)d_in[29];
    const float* W_f = (const float*)d_in[30];
    const float* b_f = (const float*)d_in[31];
    float* out = (float*)d_out;

    float *p_sumfeat, *p_simg, *p_word, *p_sumword, *p_phrase, *p_sumphrase, *p_xg;
    float *p_h, *p_h2, *p_c, *p_ss, *p_pw, *p_hw, *p_hp, *p_hs, *p_cat, *p_blp;
    SYM(p_sumfeat, g_sumfeat); SYM(p_simg, g_simg); SYM(p_word, g_word);
    SYM(p_sumword, g_sumword); SYM(p_phrase, g_phrase); SYM(p_sumphrase, g_sumphrase);
    SYM(p_xg, g_xg); SYM(p_h, g_h); SYM(p_h2, g_h2); SYM(p_c, g_c); SYM(p_ss, g_ss);
    SYM(p_pw, g_pw); SYM(p_hw, g_hw); SYM(p_hp, g_hp); SYM(p_hs, g_hs);
    SYM(p_cat, g_cat); SYM(p_blp, g_blp);

    __nv_bfloat16 *tri_h,*tri_l,*bi_h,*bi_l,*uni_h,*uni_l,*wx_h,*wx_l,*wh_h,*wh_l;
    __nv_bfloat16 *wip_h,*wip_l,*ww_h,*ww_l,*wp_h,*wp_l,*ws_h,*ws_l,*wf_h,*wf_l;
    SYM(tri_h, g_tri_h); SYM(tri_l, g_tri_l); SYM(bi_h, g_bi_h); SYM(bi_l, g_bi_l);
    SYM(uni_h, g_uni_h); SYM(uni_l, g_uni_l); SYM(wx_h, g_wx_h); SYM(wx_l, g_wx_l);
    SYM(wh_h, g_wh_h); SYM(wh_l, g_wh_l); SYM(wip_h, g_wip_h); SYM(wip_l, g_wip_l);
    SYM(ww_h, g_ww_h); SYM(ww_l, g_ww_l); SYM(wp_h, g_wp_h); SYM(wp_l, g_wp_l);
    SYM(ws_h, g_ws_h); SYM(ws_l, g_ws_l); SYM(wf_h, g_wf_h); SYM(wf_l, g_wf_l);

    const int BT = NB * TQ;          // 6656
    const int BD = NB * DH;          // 131072
    dim3 tb(32, 8);

    // conv temps inside g_xg (overwritten later by xg GEMM, after max3 consumed them)
    float* tmp_u = p_xg;
    float* tmp_b = p_xg + (size_t)BT * DH;
    float* tmp_t = p_xg + (size_t)2 * BT * DH;

    // ---- weight prep ----
    transp_hilo<<<dim3(16, 48), tb>>>(W_tri, tri_h, tri_l, 1536, 512, 512, 0);
    transp_hilo<<<dim3(16, 32), tb>>>(W_bi,  bi_h,  bi_l,  1024, 512, 512, 0);
    transp_hilo<<<dim3(16, 16), tb>>>(W_uni, uni_h, uni_l, 512, 512, 512, 0);
    transp_hilo<<<dim3(64, 16), tb>>>(Wx, wx_h, wx_l, 512, 2048, 2048, 1);
    transp_hilo<<<dim3(64, 16), tb>>>(Wh, wh_h, wh_l, 512, 2048, 2048, 1);
    transp_hilo<<<dim3(16, 16), tb>>>(W_ip, wip_h, wip_l, 512, 512, 512, 0);
    transp_hilo<<<dim3(16, 16), tb>>>(W_w, ww_h, ww_l, 512, 512, 512, 0);
    transp_hilo<<<dim3(16, 32), tb>>>(W_p, wp_h, wp_l, 1024, 512, 512, 0);
    transp_hilo<<<dim3(16, 32), tb>>>(W_s, ws_h, ws_l, 1024, 512, 512, 0);
    transp_hilo<<<dim3(96, 16), tb>>>(W_f, wf_h, wf_l, 512, NAV, NAVP, 0);
    biasperm_k<<<8, 256>>>(b_lstm, p_blp);

    // ---- image path: s_img = (sum_r image_feat) @ W_ip + RG * b_ip ----
    reduce_img_k<<<NB, 128>>>(image_feat, p_sumfeat);
    gemm_mma<EPI_BSCL><<<dim3(8, 2), 256>>>(
        p_sumfeat, wip_h, wip_l, b_ip, nullptr, p_simg, nullptr, nullptr,
        DH, DH, DH, DH, 0, (float)RG, 0, 0);

    // ---- word / phrase ----
    gather_k<<<BT, 128>>>(q_enc, emb, p_word);
    sum_t_k<<<NB, DH>>>(p_word, p_sumword);

    // n-gram convs as windowed GEMMs (woff, Kwin), biases added in epilogue
    gemm_mma<EPI_BIAS><<<dim3(8, BT / 128), 256>>>(
        p_word, uni_h, uni_l, b_uni, nullptr, tmp_u, nullptr, nullptr,
        DH, 512, DH, DH, 0, 0.f, 1, 512);
    gemm_mma<EPI_BIAS><<<dim3(8, BT / 128), 256>>>(
        p_word, bi_h, bi_l, b_bi, nullptr, tmp_b, nullptr, nullptr,
        DH, 1024, DH, DH, 0, 0.f, 1, 256);
    gemm_mma<EPI_BIAS><<<dim3(8, BT / 128), 256>>>(
        p_word, tri_h, tri_l, b_tri, nullptr, tmp_t, nullptr, nullptr,
        DH, 1536, DH, DH, 0, 0.f, 1, 0);
    max3_k<<<(BT * DH) / 256, 256>>>(tmp_u, tmp_b, tmp_t, p_phrase);
    sum_t_k<<<NB, DH>>>(p_phrase, p_sumphrase);

    // ---- xg = phrase @ Wx + b_lstm (permuted gate layout) ----
    gemm_mma<EPI_BIAS><<<dim3(32, BT / 128), 256>>>(
        p_phrase, wx_h, wx_l, p_blp, nullptr, p_xg, nullptr, nullptr,
        4 * DH, DH, DH, 4 * DH, 0, 0.f, 0, 0);

    // ---- LSTM: fused cell update in epilogue; h ping-pongs ----
    zero3_k<<<BD / 256, 256>>>(p_h, p_c, p_ss);
    for (int t = 0; t < TQ; t++) {
        float* hin  = (t & 1) ? p_h2 : p_h;
        float* hout = (t & 1) ? p_h : p_h2;
        gemm_mma<EPI_LSTM><<<dim3(32, 2), 256>>>(
            hin, wh_h, wh_l, nullptr, p_xg + (size_t)t * 4 * DH, hout, p_c, p_ss,
            4 * DH, DH, DH, 4 * DH, TQ * 4 * DH, 0.f, 0, 0);
    }

    // ---- heads (pool == plain sums; attention graph dead) ----
    add2_k<<<BD / 256, 256>>>(p_simg, p_sumword, p_pw);
    gemm_mma<EPI_TANH><<<dim3(8, 2), 256>>>(
        p_pw, ww_h, ww_l, b_w, nullptr, p_hw, nullptr, nullptr,
        DH, DH, DH, DH, 0, 0.f, 0, 0);
    cat_k<<<BD / 256, 256>>>(p_simg, p_sumphrase, p_hw, p_cat);
    gemm_mma<EPI_TANH><<<dim3(8, 2), 256>>>(
        p_cat, wp_h, wp_l, b_p, nullptr, p_hp, nullptr, nullptr,
        DH, 1024, 2 * DH, DH, 0, 0.f, 0, 0);
    cat_k<<<BD / 256, 256>>>(p_simg, p_ss, p_hp, p_cat);
    gemm_mma<EPI_TANH><<<dim3(8, 2), 256>>>(
        p_cat, ws_h, ws_l, b_s, nullptr, p_hs, nullptr, nullptr,
        DH, 1024, 2 * DH, DH, 0, 0.f, 0, 0);

    // ---- final projection ----
    gemm_mma<EPI_BIAS><<<dim3(NAVP / 64, 2), 256>>>(
        p_hs, wf_h, wf_l, b_f, nullptr, out, nullptr, nullptr,
        NAV, DH, DH, NAV, 0, 0.f, 0, 0);
}